// round 10
// baseline (speedup 1.0000x reference)
#include <cuda_runtime.h>

#define TT 256

// Ping-pong scratch (static device arrays: no allocation anywhere).
__device__ float g_bufX[33554432];
__device__ float g_bufY[33554432];

__device__ __forceinline__ void ffma2(unsigned long long& acc,
                                      unsigned long long w,
                                      unsigned long long v) {
    asm("fma.rn.f32x2 %0, %1, %2, %0;" : "+l"(acc) : "l"(w), "l"(v));
}

// ---------------------------------------------------------------------------
// Standalone dynamics kernel (input-psp, pool, upsample layers).
// MODE 0: psp only
// MODE 2: sumpool2 + spike + psp (4-tap gather fused)
// MODE 3: bilinear-up2 + spike + psp (4-tap gather fused)
// Double-buffered register prefetch with NAMED buffers (compile-time indices).
// ---------------------------------------------------------------------------
template<int MODE>
__global__ void dyn_kernel(const float* __restrict__ in, float* __restrict__ out,
                           int H, int W, int N)
{
    int n = blockIdx.x * blockDim.x + threadIdx.x;
    if (n >= N) return;

    const float dsr  = 0.9048374180359595f;   // exp(-1/10)
    const float psc  = 0.27182818284590452f;  // e/10
    const float dref = 0.36787944117144233f;  // exp(-1)

    constexpr int S  = (MODE == 2 || MODE == 3) ? 4 : 1;
    constexpr int CH = (S == 4) ? 8 : 16;
    constexpr int F4 = CH / 4;
    constexpr int NC = TT / CH;              // even

    const float* p[S];
    float w00 = 0.f, w01 = 0.f, w10 = 0.f, w11 = 0.f;

    if (MODE == 2) {
        int x = n % W, y = (n / W) % H, bc = n / (W * H);
        int Win = 2 * W;
        const float* base = in + (((long)bc * (2 * H) + 2 * y) * Win + 2 * x) * TT;
        p[0] = base;
        p[1] = base + TT;
        p[2] = base + (long)Win * TT;
        p[3] = base + (long)(Win + 1) * TT;
    } else if (MODE == 3) {
        int x = n % W, y = (n / W) % H, bc = n / (W * H);
        int Hin = H / 2, Win = W / 2;
        int jy = y >> 1, jx = x >> 1;
        int ya, yb, xa, xb; float wya, wyb, wxa, wxb;
        if ((y & 1) == 0) { ya = (jy > 0) ? jy - 1 : 0; yb = jy; wya = 0.25f; wyb = 0.75f; }
        else              { ya = jy; yb = (jy + 1 < Hin) ? jy + 1 : Hin - 1; wya = 0.75f; wyb = 0.25f; }
        if ((x & 1) == 0) { xa = (jx > 0) ? jx - 1 : 0; xb = jx; wxa = 0.25f; wxb = 0.75f; }
        else              { xa = jx; xb = (jx + 1 < Win) ? jx + 1 : Win - 1; wxa = 0.75f; wxb = 0.25f; }
        const float* base = in + (long)bc * Hin * Win * TT;
        p[0] = base + ((long)ya * Win + xa) * TT; w00 = wya * wxa;
        p[1] = base + ((long)ya * Win + xb) * TT; w01 = wya * wxb;
        p[2] = base + ((long)yb * Win + xa) * TT; w10 = wyb * wxa;
        p[3] = base + ((long)yb * Win + xb) * TT; w11 = wyb * wxb;
    } else {
        p[0] = in + (long)n * TT;
    }

    float* ob = out + (long)n * TT;

    float g1 = 0.f, g2 = 0.f, r = 0.f;

    float4 A[S][F4], B[S][F4];

    auto load = [&](float4 (&buf)[S][F4], int c) {
        #pragma unroll
        for (int s = 0; s < S; s++)
            #pragma unroll
            for (int f = 0; f < F4; f++)
                buf[s][f] = *(const float4*)(p[s] + c * CH + f * 4);
    };

    auto compute = [&](float4 (&buf)[S][F4], int c) {
        #pragma unroll
        for (int f = 0; f < F4; f++) {
            float u[4];
            if (MODE == 2) {
                float4 a = buf[0][f], b = buf[1][f], cc = buf[2][f], d = buf[3][f];
                u[0] = 2.75f * ((a.x + b.x) + (cc.x + d.x));
                u[1] = 2.75f * ((a.y + b.y) + (cc.y + d.y));
                u[2] = 2.75f * ((a.z + b.z) + (cc.z + d.z));
                u[3] = 2.75f * ((a.w + b.w) + (cc.w + d.w));
            } else if (MODE == 3) {
                float4 a = buf[0][f], b = buf[1][f], cc = buf[2][f], d = buf[3][f];
                u[0] = w00 * a.x + w01 * b.x + w10 * cc.x + w11 * d.x;
                u[1] = w00 * a.y + w01 * b.y + w10 * cc.y + w11 * d.y;
                u[2] = w00 * a.z + w01 * b.z + w10 * cc.z + w11 * d.z;
                u[3] = w00 * a.w + w01 * b.w + w10 * cc.w + w11 * d.w;
            } else {
                float4 a = buf[0][f];
                u[0] = a.x; u[1] = a.y; u[2] = a.z; u[3] = a.w;
            }
            float o[4];
            #pragma unroll
            for (int j = 0; j < 4; j++) {
                if (MODE == 0) {
                    g1 = fmaf(dsr, g1, u[j]);
                    g2 = fmaf(dsr, g2, g1);
                    o[j] = psc * (g2 - g1);
                } else {
                    float v = u[j] + r - 10.0f;
                    float s = (v >= 0.f) ? 1.f : 0.f;
                    r = dref * (r - 20.f * s);
                    g1 = fmaf(dsr, g1, s);
                    g2 = fmaf(dsr, g2, g1);
                    o[j] = psc * (g2 - g1);
                }
            }
            *(float4*)(ob + c * CH + f * 4) = make_float4(o[0], o[1], o[2], o[3]);
        }
    };

    load(A, 0);
    for (int c = 0; c < NC; c += 2) {
        load(B, c + 1);
        compute(A, c);
        if (c + 2 < NC) load(A, c + 2);
        compute(B, c + 1);
    }
}

// ---------------------------------------------------------------------------
// Fused conv + spike/psp epilogue with 2-PIXEL COLUMN SHARING.
// Block = 64 threads covering all 256 timesteps (TW=4 each), computing
// PX=2 x-adjacent output pixels x OCG channels. Per (kh, ic) the block loads
// KS+1 input columns ONCE; pixel p, tap dx reuses column v[dx+p]. Each loaded
// value feeds PX*OCG FMAs -> FFMA2 is >80% of inner-loop instructions while
// acc stays at PX*OCG*2 u64 (32 regs for OCG=4).
// Weight table and activation staging buffer are UNIONED in smem.
// EPI = 1: spike + psp.  EPI = 4: spike only (final layer).
// ---------------------------------------------------------------------------
template<int IC, int KS, int PAD, int OCG, int EPI>
__global__ __launch_bounds__(64)
void conv_kernel(const float* __restrict__ in, const float* __restrict__ wgt,
                 float* __restrict__ out, int H, int W, int OC)
{
    constexpr int PX   = 2;
    constexpr int NCOL = KS + PX - 1;
    constexpr int SW_BYTES = IC * KS * KS * OCG * 8;
    constexpr int SA_BYTES = PX * OCG * 260 * 4;
    constexpr int SM_BYTES = SW_BYTES > SA_BYTES ? SW_BYTES : SA_BYTES;
    __shared__ __align__(16) unsigned char smem_raw[SM_BYTES];
    unsigned long long* sw = (unsigned long long*)smem_raw;
    float* sa = (float*)smem_raw;           // rows: [PX*OCG][260]

    int tid = threadIdx.x;
    int t   = tid * 4;

    int W2 = W >> 1;
    int pp = blockIdx.x;
    int x0 = (pp % W2) * 2;
    int y  = (pp / W2) % H;
    int b  = pp / (W2 * H);
    int oc0 = blockIdx.y * OCG;

    for (int i = tid; i < IC * KS * KS * OCG; i += 64) {
        int k = i / OCG, o = i % OCG;
        unsigned u = __float_as_uint(wgt[(long)(oc0 + o) * IC * KS * KS + k]);
        sw[i] = ((unsigned long long)u << 32) | u;
    }
    __syncthreads();

    unsigned long long acc[PX][OCG][2];
    #pragma unroll
    for (int p = 0; p < PX; p++)
        #pragma unroll
        for (int o = 0; o < OCG; o++) { acc[p][o][0] = 0ull; acc[p][o][1] = 0ull; }

    const long planeT = (long)H * W * TT;
    const float* inb = in + (long)b * IC * planeT + t;

    #pragma unroll
    for (int kh = 0; kh < KS; kh++) {
        int yy = y + kh - PAD;
        if (yy < 0 || yy >= H) continue;
        const float* rowb = inb + (long)yy * W * TT;
        #pragma unroll 2
        for (int ic = 0; ic < IC; ic++) {
            const float* icb = rowb + (long)ic * planeT;
            ulonglong2 v[NCOL];
            #pragma unroll
            for (int j = 0; j < NCOL; j++) {
                int c = x0 - PAD + j;
                if (c >= 0 && c < W) v[j] = *(const ulonglong2*)(icb + (long)c * TT);
                else                 v[j] = make_ulonglong2(0ull, 0ull);
            }
            #pragma unroll
            for (int dx = 0; dx < KS; dx++) {
                const unsigned long long* swp = &sw[(ic * KS * KS + kh * KS + dx) * OCG];
                if constexpr (OCG % 2 == 0) {
                    #pragma unroll
                    for (int o = 0; o < OCG; o += 2) {
                        ulonglong2 wv = *(const ulonglong2*)(swp + o);
                        #pragma unroll
                        for (int p = 0; p < PX; p++) {
                            ffma2(acc[p][o    ][0], wv.x, v[dx + p].x);
                            ffma2(acc[p][o    ][1], wv.x, v[dx + p].y);
                            ffma2(acc[p][o + 1][0], wv.y, v[dx + p].x);
                            ffma2(acc[p][o + 1][1], wv.y, v[dx + p].y);
                        }
                    }
                } else {
                    #pragma unroll
                    for (int o = 0; o < OCG; o++) {
                        unsigned long long wv = swp[o];
                        #pragma unroll
                        for (int p = 0; p < PX; p++) {
                            ffma2(acc[p][o][0], wv, v[dx + p].x);
                            ffma2(acc[p][o][1], wv, v[dx + p].y);
                        }
                    }
                }
            }
        }
    }

    // All threads done reading sw -> safe to overwrite with sa.
    __syncthreads();

    #pragma unroll
    for (int p = 0; p < PX; p++)
        #pragma unroll
        for (int o = 0; o < OCG; o++) {
            float* sap = sa + (p * OCG + o) * 260 + t;
            *(float2*)(sap    ) = *(float2*)&acc[p][o][0];
            *(float2*)(sap + 2) = *(float2*)&acc[p][o][1];
        }
    __syncthreads();

    // Per-(pixel,channel) serial recurrence over T (PX*OCG threads; hidden
    // under the conv mainloops of co-resident blocks).
    if (tid < PX * OCG) {
        const float dsr  = 0.9048374180359595f;
        const float psc  = 0.27182818284590452f;
        const float dref = 0.36787944117144233f;
        float* row = sa + tid * 260;
        float g1 = 0.f, g2 = 0.f, r = 0.f;
        float4 nxt = *(float4*)row;
        for (int tt = 0; tt < TT; tt += 4) {
            float4 a = nxt;
            if (tt + 4 < TT) nxt = *(float4*)(row + tt + 4);
            float u[4] = {a.x, a.y, a.z, a.w};
            float o4[4];
            #pragma unroll
            for (int j = 0; j < 4; j++) {
                float v = u[j] + r - 10.0f;
                float s = (v >= 0.f) ? 1.f : 0.f;
                r = dref * (r - 20.f * s);
                if (EPI == 4) {
                    o4[j] = s;
                } else {
                    g1 = fmaf(dsr, g1, s);
                    g2 = fmaf(dsr, g2, g1);
                    o4[j] = psc * (g2 - g1);
                }
            }
            *(float4*)(row + tt) = make_float4(o4[0], o4[1], o4[2], o4[3]);
        }
    }
    __syncthreads();

    // Coalesced float4 stores of the PSP (or spike) tensor.
    #pragma unroll
    for (int p = 0; p < PX; p++) {
        float* ob = out + ((long)b * OC + oc0) * planeT + ((long)y * W + x0 + p) * TT + t;
        #pragma unroll
        for (int o = 0; o < OCG; o++)
            *(float4*)(ob + (long)o * planeT) = *(const float4*)(sa + (p * OCG + o) * 260 + t);
    }
}

// ---------------------------------------------------------------------------
// 10 launches, ping-pong X<->Y.
// ---------------------------------------------------------------------------
extern "C" void kernel_launch(void* const* d_in, const int* in_sizes, int n_in,
                              void* d_out, int out_size)
{
    const float* inp = (const float*)d_in[0];  // [4,1,32,32,256]
    const float* w1  = (const float*)d_in[1];  // [16,1,5,5,1]
    const float* w2  = (const float*)d_in[2];  // [32,16,3,3,1]
    const float* w3  = (const float*)d_in[3];  // [64,32,3,3,1]
    const float* w4  = (const float*)d_in[4];  // [32,64,3,3,1]
    const float* wo  = (const float*)d_in[5];  // [1,32,1,1,1]
    float* out = (float*)d_out;

    float *X, *Y;
    cudaGetSymbolAddress((void**)&X, g_bufX);
    cudaGetSymbolAddress((void**)&Y, g_bufY);

    // P0 = psp(input) -> X        (N=4096)
    dyn_kernel<0><<<128, 32>>>(inp, X, 32, 32, 4096);

    // P1 = spike/psp(conv1(P0)) -> Y      OCG=8, pairs=2048, grid.y=2
    conv_kernel<1, 5, 2, 8, 1><<<dim3(2048, 2), 64>>>(X, w1, Y, 32, 32, 16);

    // P2 = pool+spike+psp(P1) -> X   [4,16,16,16]
    dyn_kernel<2><<<256, 64>>>(Y, X, 16, 16, 16384);

    // P3 = spike/psp(conv2(P2)) -> Y      OCG=4, pairs=512, grid.y=8
    conv_kernel<16, 3, 1, 4, 1><<<dim3(512, 8), 64>>>(X, w2, Y, 16, 16, 32);

    // P4 = pool+spike+psp(P3) -> X   [4,32,8,8]
    dyn_kernel<2><<<256, 32>>>(Y, X, 8, 8, 8192);

    // P5 = spike/psp(conv3(P4)) -> Y      OCG=4, pairs=128, grid.y=16
    conv_kernel<32, 3, 1, 4, 1><<<dim3(128, 16), 64>>>(X, w3, Y, 8, 8, 64);

    // P6 = up+spike+psp(P5) -> X   [4,64,16,16]
    dyn_kernel<3><<<512, 128>>>(Y, X, 16, 16, 65536);

    // P7 = spike/psp(conv4(P6)) -> Y      OCG=4, pairs=512, grid.y=8
    conv_kernel<64, 3, 1, 4, 1><<<dim3(512, 8), 64>>>(X, w4, Y, 16, 16, 32);

    // P8 = up+spike+psp(P7) -> X   [4,32,32,32]
    dyn_kernel<3><<<1024, 128>>>(Y, X, 32, 32, 131072);

    // out = spike(conv_out(P8))   OCG=1, pairs=2048
    conv_kernel<32, 1, 0, 1, 4><<<dim3(2048, 1), 64>>>(X, wo, out, 32, 32, 1);
}

// round 11
// speedup vs baseline: 1.1861x; 1.1861x over previous
#include <cuda_runtime.h>

#define TT 256

// ---------------------------------------------------------------------------
// Workspace: ONE static device array, dedicated (non-aliased) regions per
// tensor. Device globals are zero-initialized at module load; producers write
// only tensor interiors, so the spatial halos of padded layouts stay zero
// forever -> conv kernels need no bounds checks at all.
// Layout per tensor: [B, C, H+2P, W+2P, T], halo P = consumer conv's padding.
// ---------------------------------------------------------------------------
// sizes (floats):
//  P0p [4,1,36,36,256]   = 1,327,104   (conv1 pad 2)
//  P1  [4,16,32,32,256]  = 16,777,216
//  P2p [4,16,18,18,256]  = 5,308,416   (conv2 pad 1)
//  P3  [4,32,16,16,256]  = 8,388,608
//  P4p [4,32,10,10,256]  = 3,276,800   (conv3 pad 1)
//  P5  [4,64,8,8,256]    = 4,194,304
//  P6p [4,64,18,18,256]  = 21,233,664  (conv4 pad 1)
//  P7  [4,32,16,16,256]  = 8,388,608
//  P8  [4,32,32,32,256]  = 33,554,432  (conv_out pad 0)
#define O_P0 0L
#define O_P1 1327104L
#define O_P2 18104320L
#define O_P3 23412736L
#define O_P4 31801344L
#define O_P5 35078144L
#define O_P6 39272448L
#define O_P7 60506112L
#define O_P8 68894720L
#define WS_TOTAL 102449152L
__device__ float g_ws[WS_TOTAL];

__device__ __forceinline__ void ffma2(unsigned long long& acc,
                                      unsigned long long w,
                                      unsigned long long v) {
    asm("fma.rn.f32x2 %0, %1, %2, %0;" : "+l"(acc) : "l"(w), "l"(v));
}

// ---------------------------------------------------------------------------
// Standalone dynamics kernel (input-psp, pool, upsample layers).
// MODE 0: psp only
// MODE 2: sumpool2 + spike + psp (4-tap gather fused)
// MODE 3: bilinear-up2 + spike + psp (4-tap gather fused)
// H, W: OUTPUT spatial dims (compile-time). OPAD: output halo (writes go to
// the interior of a padded layout). Inputs are always unpadded layouts.
// Double-buffered register prefetch with NAMED buffers.
// ---------------------------------------------------------------------------
template<int MODE, int H, int W, int OPAD>
__global__ void dyn_kernel(const float* __restrict__ in, float* __restrict__ out,
                           int N)
{
    int n = blockIdx.x * blockDim.x + threadIdx.x;
    if (n >= N) return;

    const float dsr  = 0.9048374180359595f;   // exp(-1/10)
    const float psc  = 0.27182818284590452f;  // e/10
    const float dref = 0.36787944117144233f;  // exp(-1)

    constexpr int S  = (MODE == 2 || MODE == 3) ? 4 : 1;
    constexpr int CH = (S == 4) ? 8 : 16;
    constexpr int F4 = CH / 4;
    constexpr int NC = TT / CH;              // even
    constexpr int Ho = H + 2 * OPAD;
    constexpr int Wo = W + 2 * OPAD;

    int x = n % W, y = (n / W) % H, bc = n / (W * H);

    const float* p[S];
    float w00 = 0.f, w01 = 0.f, w10 = 0.f, w11 = 0.f;

    if (MODE == 2) {
        constexpr int Win = 2 * W;
        const float* base = in + (((long)bc * (2 * H) + 2 * y) * Win + 2 * x) * TT;
        p[0] = base;
        p[1] = base + TT;
        p[2] = base + (long)Win * TT;
        p[3] = base + (long)(Win + 1) * TT;
    } else if (MODE == 3) {
        constexpr int Hin = H / 2, Win = W / 2;
        int jy = y >> 1, jx = x >> 1;
        int ya, yb, xa, xb; float wya, wyb, wxa, wxb;
        if ((y & 1) == 0) { ya = (jy > 0) ? jy - 1 : 0; yb = jy; wya = 0.25f; wyb = 0.75f; }
        else              { ya = jy; yb = (jy + 1 < Hin) ? jy + 1 : Hin - 1; wya = 0.75f; wyb = 0.25f; }
        if ((x & 1) == 0) { xa = (jx > 0) ? jx - 1 : 0; xb = jx; wxa = 0.25f; wxb = 0.75f; }
        else              { xa = jx; xb = (jx + 1 < Win) ? jx + 1 : Win - 1; wxa = 0.75f; wxb = 0.25f; }
        const float* base = in + (long)bc * Hin * Win * TT;
        p[0] = base + ((long)ya * Win + xa) * TT; w00 = wya * wxa;
        p[1] = base + ((long)ya * Win + xb) * TT; w01 = wya * wxb;
        p[2] = base + ((long)yb * Win + xa) * TT; w10 = wyb * wxa;
        p[3] = base + ((long)yb * Win + xb) * TT; w11 = wyb * wxb;
    } else {
        p[0] = in + (long)n * TT;
    }

    float* ob = out + (((long)bc * Ho + (y + OPAD)) * Wo + (x + OPAD)) * TT;

    float g1 = 0.f, g2 = 0.f, r = 0.f;

    float4 A[S][F4], B[S][F4];

    auto load = [&](float4 (&buf)[S][F4], int c) {
        #pragma unroll
        for (int s = 0; s < S; s++)
            #pragma unroll
            for (int f = 0; f < F4; f++)
                buf[s][f] = *(const float4*)(p[s] + c * CH + f * 4);
    };

    auto compute = [&](float4 (&buf)[S][F4], int c) {
        #pragma unroll
        for (int f = 0; f < F4; f++) {
            float u[4];
            if (MODE == 2) {
                float4 a = buf[0][f], b = buf[1][f], cc = buf[2][f], d = buf[3][f];
                u[0] = 2.75f * ((a.x + b.x) + (cc.x + d.x));
                u[1] = 2.75f * ((a.y + b.y) + (cc.y + d.y));
                u[2] = 2.75f * ((a.z + b.z) + (cc.z + d.z));
                u[3] = 2.75f * ((a.w + b.w) + (cc.w + d.w));
            } else if (MODE == 3) {
                float4 a = buf[0][f], b = buf[1][f], cc = buf[2][f], d = buf[3][f];
                u[0] = w00 * a.x + w01 * b.x + w10 * cc.x + w11 * d.x;
                u[1] = w00 * a.y + w01 * b.y + w10 * cc.y + w11 * d.y;
                u[2] = w00 * a.z + w01 * b.z + w10 * cc.z + w11 * d.z;
                u[3] = w00 * a.w + w01 * b.w + w10 * cc.w + w11 * d.w;
            } else {
                float4 a = buf[0][f];
                u[0] = a.x; u[1] = a.y; u[2] = a.z; u[3] = a.w;
            }
            float o[4];
            #pragma unroll
            for (int j = 0; j < 4; j++) {
                if (MODE == 0) {
                    g1 = fmaf(dsr, g1, u[j]);
                    g2 = fmaf(dsr, g2, g1);
                    o[j] = psc * (g2 - g1);
                } else {
                    float v = u[j] + r - 10.0f;
                    float s = (v >= 0.f) ? 1.f : 0.f;
                    r = dref * (r - 20.f * s);
                    g1 = fmaf(dsr, g1, s);
                    g2 = fmaf(dsr, g2, g1);
                    o[j] = psc * (g2 - g1);
                }
            }
            *(float4*)(ob + c * CH + f * 4) = make_float4(o[0], o[1], o[2], o[3]);
        }
    };

    load(A, 0);
    for (int c = 0; c < NC; c += 2) {
        load(B, c + 1);
        compute(A, c);
        if (c + 2 < NC) load(A, c + 2);
        compute(B, c + 1);
    }
}

// ---------------------------------------------------------------------------
// Fused conv + spike/psp epilogue over ZERO-PADDED input.
// Block = 64 threads (TW=4 timesteps each), PX=2 x-adjacent pixels, OCG chans.
// Input layout is halo-padded -> NO bounds checks anywhere; all column loads
// are unconditional LDG.128 at compile-time offsets. Per (kh,ic):
//   NCOL LDG.128 + KS*(OCG/2) LDS.128 + KS*PX*OCG*2 fma.rn.f32x2.
// Weight table and activation staging buffer are UNIONED in smem.
// EPI = 1: spike + psp.  EPI = 4: spike only (final layer).
// ---------------------------------------------------------------------------
template<int IC, int KS, int OCG, int EPI, int H, int W, int OC>
__global__ __launch_bounds__(64)
void conv_kernel(const float* __restrict__ in, const float* __restrict__ wgt,
                 float* __restrict__ out)
{
    constexpr int PAD  = KS / 2;
    constexpr int Hp   = H + 2 * PAD;
    constexpr int Wp   = W + 2 * PAD;
    constexpr int PX   = 2;
    constexpr int NCOL = KS + PX - 1;
    constexpr int W2   = W / 2;
    constexpr int SW_BYTES = IC * KS * KS * OCG * 8;
    constexpr int SA_BYTES = PX * OCG * 260 * 4;
    constexpr int SM_BYTES = SW_BYTES > SA_BYTES ? SW_BYTES : SA_BYTES;
    __shared__ __align__(16) unsigned char smem_raw[SM_BYTES];
    unsigned long long* sw = (unsigned long long*)smem_raw;
    float* sa = (float*)smem_raw;           // rows: [PX*OCG][260]

    int tid = threadIdx.x;
    int t   = tid * 4;

    int pp = blockIdx.x;
    int x0 = (pp % W2) * 2;
    int y  = (pp / W2) % H;
    int b  = pp / (W2 * H);
    int oc0 = blockIdx.y * OCG;

    for (int i = tid; i < IC * KS * KS * OCG; i += 64) {
        int k = i / OCG, o = i % OCG;
        unsigned u = __float_as_uint(wgt[(long)(oc0 + o) * IC * KS * KS + k]);
        sw[i] = ((unsigned long long)u << 32) | u;
    }
    __syncthreads();

    unsigned long long acc[PX][OCG][2];
    #pragma unroll
    for (int p = 0; p < PX; p++)
        #pragma unroll
        for (int o = 0; o < OCG; o++) { acc[p][o][0] = 0ull; acc[p][o][1] = 0ull; }

    constexpr long planeTp = (long)Hp * Wp * TT;
    // Padded coords: output pixel (y, x0) window starts at padded (y, x0).
    const float* inb = in + ((long)b * IC * Hp + y) * (long)Wp * TT + (long)x0 * TT + t;

    #pragma unroll
    for (int kh = 0; kh < KS; kh++) {
        const float* rp = inb + (long)kh * Wp * TT;
        #pragma unroll 4
        for (int ic = 0; ic < IC; ic++) {
            const float* icb = rp + (long)ic * planeTp;
            ulonglong2 v[NCOL];
            #pragma unroll
            for (int j = 0; j < NCOL; j++)
                v[j] = *(const ulonglong2*)(icb + j * TT);
            #pragma unroll
            for (int dx = 0; dx < KS; dx++) {
                const unsigned long long* swp = &sw[(ic * KS * KS + kh * KS + dx) * OCG];
                if constexpr (OCG % 2 == 0) {
                    #pragma unroll
                    for (int o = 0; o < OCG; o += 2) {
                        ulonglong2 wv = *(const ulonglong2*)(swp + o);
                        #pragma unroll
                        for (int p = 0; p < PX; p++) {
                            ffma2(acc[p][o    ][0], wv.x, v[dx + p].x);
                            ffma2(acc[p][o    ][1], wv.x, v[dx + p].y);
                            ffma2(acc[p][o + 1][0], wv.y, v[dx + p].x);
                            ffma2(acc[p][o + 1][1], wv.y, v[dx + p].y);
                        }
                    }
                } else {
                    #pragma unroll
                    for (int o = 0; o < OCG; o++) {
                        unsigned long long wv = swp[o];
                        #pragma unroll
                        for (int p = 0; p < PX; p++) {
                            ffma2(acc[p][o][0], wv, v[dx + p].x);
                            ffma2(acc[p][o][1], wv, v[dx + p].y);
                        }
                    }
                }
            }
        }
    }

    // All threads done reading sw -> safe to overwrite with sa.
    __syncthreads();

    #pragma unroll
    for (int p = 0; p < PX; p++)
        #pragma unroll
        for (int o = 0; o < OCG; o++) {
            float* sap = sa + (p * OCG + o) * 260 + t;
            *(float2*)(sap    ) = *(float2*)&acc[p][o][0];
            *(float2*)(sap + 2) = *(float2*)&acc[p][o][1];
        }
    __syncthreads();

    // Per-(pixel,channel) serial recurrence over T (PX*OCG threads).
    if (tid < PX * OCG) {
        const float dsr  = 0.9048374180359595f;
        const float psc  = 0.27182818284590452f;
        const float dref = 0.36787944117144233f;
        float* row = sa + tid * 260;
        float g1 = 0.f, g2 = 0.f, r = 0.f;
        float4 nxt = *(float4*)row;
        for (int tt = 0; tt < TT; tt += 4) {
            float4 a = nxt;
            if (tt + 4 < TT) nxt = *(float4*)(row + tt + 4);
            float u[4] = {a.x, a.y, a.z, a.w};
            float o4[4];
            #pragma unroll
            for (int j = 0; j < 4; j++) {
                float v = u[j] + r - 10.0f;
                float s = (v >= 0.f) ? 1.f : 0.f;
                r = dref * (r - 20.f * s);
                if (EPI == 4) {
                    o4[j] = s;
                } else {
                    g1 = fmaf(dsr, g1, s);
                    g2 = fmaf(dsr, g2, g1);
                    o4[j] = psc * (g2 - g1);
                }
            }
            *(float4*)(row + tt) = make_float4(o4[0], o4[1], o4[2], o4[3]);
        }
    }
    __syncthreads();

    // Coalesced float4 stores to the UNPADDED output layout.
    constexpr long planeT = (long)H * W * TT;
    #pragma unroll
    for (int p = 0; p < PX; p++) {
        float* ob = out + ((long)b * OC + oc0) * planeT + ((long)y * W + x0 + p) * TT + t;
        #pragma unroll
        for (int o = 0; o < OCG; o++)
            *(float4*)(ob + o * planeT) = *(const float4*)(sa + (p * OCG + o) * 260 + t);
    }
}

// ---------------------------------------------------------------------------
// 10 launches; every tensor has a dedicated workspace region (halos stay 0).
// ---------------------------------------------------------------------------
extern "C" void kernel_launch(void* const* d_in, const int* in_sizes, int n_in,
                              void* d_out, int out_size)
{
    const float* inp = (const float*)d_in[0];  // [4,1,32,32,256]
    const float* w1  = (const float*)d_in[1];  // [16,1,5,5,1]
    const float* w2  = (const float*)d_in[2];  // [32,16,3,3,1]
    const float* w3  = (const float*)d_in[3];  // [64,32,3,3,1]
    const float* w4  = (const float*)d_in[4];  // [32,64,3,3,1]
    const float* wo  = (const float*)d_in[5];  // [1,32,1,1,1]
    float* out = (float*)d_out;

    float* WS;
    cudaGetSymbolAddress((void**)&WS, g_ws);
    float* P0 = WS + O_P0;  float* P1 = WS + O_P1;
    float* P2 = WS + O_P2;  float* P3 = WS + O_P3;
    float* P4 = WS + O_P4;  float* P5 = WS + O_P5;
    float* P6 = WS + O_P6;  float* P7 = WS + O_P7;
    float* P8 = WS + O_P8;

    // P0 = psp(input), padded 2 for conv1
    dyn_kernel<0, 32, 32, 2><<<128, 32>>>(inp, P0, 4096);

    // P1 = spike/psp(conv1(P0))
    conv_kernel<1, 5, 8, 1, 32, 32, 16><<<dim3(2048, 2), 64>>>(P0, w1, P1);

    // P2 = pool+spike+psp(P1), padded 1 for conv2   [4,16,16,16]
    dyn_kernel<2, 16, 16, 1><<<256, 64>>>(P1, P2, 16384);

    // P3 = spike/psp(conv2(P2))
    conv_kernel<16, 3, 4, 1, 16, 16, 32><<<dim3(512, 8), 64>>>(P2, w2, P3);

    // P4 = pool+spike+psp(P3), padded 1 for conv3   [4,32,8,8]
    dyn_kernel<2, 8, 8, 1><<<256, 32>>>(P3, P4, 8192);

    // P5 = spike/psp(conv3(P4))
    conv_kernel<32, 3, 4, 1, 8, 8, 64><<<dim3(128, 16), 64>>>(P4, w3, P5);

    // P6 = up+spike+psp(P5), padded 1 for conv4   [4,64,16,16]
    dyn_kernel<3, 16, 16, 1><<<512, 128>>>(P5, P6, 65536);

    // P7 = spike/psp(conv4(P6))
    conv_kernel<64, 3, 4, 1, 16, 16, 32><<<dim3(512, 8), 64>>>(P6, w4, P7);

    // P8 = up+spike+psp(P7), unpadded (conv_out is 1x1)   [4,32,32,32]
    dyn_kernel<3, 32, 32, 0><<<1024, 128>>>(P7, P8, 131072);

    // out = spike(conv_out(P8))
    conv_kernel<32, 1, 1, 4, 32, 32, 1><<<dim3(2048, 1), 64>>>(P8, wo, out);
}

// round 12
// speedup vs baseline: 1.1930x; 1.0058x over previous
#include <cuda_runtime.h>

#define TT 256

// ---------------------------------------------------------------------------
// Workspace: ONE static device array, dedicated (non-aliased) regions per
// tensor. Device globals are zero-initialized at module load; producers write
// only tensor interiors, so the spatial halos of padded layouts stay zero
// forever -> conv kernels need no bounds checks at all.
// Layout per tensor: [B, C, H+2P, W+2P, T], halo P = consumer conv's padding.
// ---------------------------------------------------------------------------
#define O_P0 0L
#define O_P1 1327104L
#define O_P2 18104320L
#define O_P3 23412736L
#define O_P4 31801344L
#define O_P5 35078144L
#define O_P6 39272448L
#define O_P7 60506112L
#define O_P8 68894720L
#define WS_TOTAL 102449152L
__device__ float g_ws[WS_TOTAL];

__device__ __forceinline__ void ffma2(unsigned long long& acc,
                                      unsigned long long w,
                                      unsigned long long v) {
    asm("fma.rn.f32x2 %0, %1, %2, %0;" : "+l"(acc) : "l"(w), "l"(v));
}

// ---------------------------------------------------------------------------
// Standalone dynamics kernel (input-psp, pool, upsample layers).
// MODE 0: psp only ; MODE 2: pool+spike+psp ; MODE 3: up2+spike+psp
// H, W: OUTPUT spatial dims (compile-time). OPAD: output halo.
// Double-buffered register prefetch with NAMED buffers.
// ---------------------------------------------------------------------------
template<int MODE, int H, int W, int OPAD>
__global__ void dyn_kernel(const float* __restrict__ in, float* __restrict__ out,
                           int N)
{
    int n = blockIdx.x * blockDim.x + threadIdx.x;
    if (n >= N) return;

    const float dsr  = 0.9048374180359595f;   // exp(-1/10)
    const float psc  = 0.27182818284590452f;  // e/10
    const float dref = 0.36787944117144233f;  // exp(-1)

    constexpr int S  = (MODE == 2 || MODE == 3) ? 4 : 1;
    constexpr int CH = (S == 4) ? 8 : 16;
    constexpr int F4 = CH / 4;
    constexpr int NC = TT / CH;
    constexpr int Ho = H + 2 * OPAD;
    constexpr int Wo = W + 2 * OPAD;

    int x = n % W, y = (n / W) % H, bc = n / (W * H);

    const float* p[S];
    float w00 = 0.f, w01 = 0.f, w10 = 0.f, w11 = 0.f;

    if (MODE == 2) {
        constexpr int Win = 2 * W;
        const float* base = in + (((long)bc * (2 * H) + 2 * y) * Win + 2 * x) * TT;
        p[0] = base;
        p[1] = base + TT;
        p[2] = base + (long)Win * TT;
        p[3] = base + (long)(Win + 1) * TT;
    } else if (MODE == 3) {
        constexpr int Hin = H / 2, Win = W / 2;
        int jy = y >> 1, jx = x >> 1;
        int ya, yb, xa, xb; float wya, wyb, wxa, wxb;
        if ((y & 1) == 0) { ya = (jy > 0) ? jy - 1 : 0; yb = jy; wya = 0.25f; wyb = 0.75f; }
        else              { ya = jy; yb = (jy + 1 < Hin) ? jy + 1 : Hin - 1; wya = 0.75f; wyb = 0.25f; }
        if ((x & 1) == 0) { xa = (jx > 0) ? jx - 1 : 0; xb = jx; wxa = 0.25f; wxb = 0.75f; }
        else              { xa = jx; xb = (jx + 1 < Win) ? jx + 1 : Win - 1; wxa = 0.75f; wxb = 0.25f; }
        const float* base = in + (long)bc * Hin * Win * TT;
        p[0] = base + ((long)ya * Win + xa) * TT; w00 = wya * wxa;
        p[1] = base + ((long)ya * Win + xb) * TT; w01 = wya * wxb;
        p[2] = base + ((long)yb * Win + xa) * TT; w10 = wyb * wxa;
        p[3] = base + ((long)yb * Win + xb) * TT; w11 = wyb * wxb;
    } else {
        p[0] = in + (long)n * TT;
    }

    float* ob = out + (((long)bc * Ho + (y + OPAD)) * Wo + (x + OPAD)) * TT;

    float g1 = 0.f, g2 = 0.f, r = 0.f;

    float4 A[S][F4], B[S][F4];

    auto load = [&](float4 (&buf)[S][F4], int c) {
        #pragma unroll
        for (int s = 0; s < S; s++)
            #pragma unroll
            for (int f = 0; f < F4; f++)
                buf[s][f] = *(const float4*)(p[s] + c * CH + f * 4);
    };

    auto compute = [&](float4 (&buf)[S][F4], int c) {
        #pragma unroll
        for (int f = 0; f < F4; f++) {
            float u[4];
            if (MODE == 2) {
                float4 a = buf[0][f], b = buf[1][f], cc = buf[2][f], d = buf[3][f];
                u[0] = 2.75f * ((a.x + b.x) + (cc.x + d.x));
                u[1] = 2.75f * ((a.y + b.y) + (cc.y + d.y));
                u[2] = 2.75f * ((a.z + b.z) + (cc.z + d.z));
                u[3] = 2.75f * ((a.w + b.w) + (cc.w + d.w));
            } else if (MODE == 3) {
                float4 a = buf[0][f], b = buf[1][f], cc = buf[2][f], d = buf[3][f];
                u[0] = w00 * a.x + w01 * b.x + w10 * cc.x + w11 * d.x;
                u[1] = w00 * a.y + w01 * b.y + w10 * cc.y + w11 * d.y;
                u[2] = w00 * a.z + w01 * b.z + w10 * cc.z + w11 * d.z;
                u[3] = w00 * a.w + w01 * b.w + w10 * cc.w + w11 * d.w;
            } else {
                float4 a = buf[0][f];
                u[0] = a.x; u[1] = a.y; u[2] = a.z; u[3] = a.w;
            }
            float o[4];
            #pragma unroll
            for (int j = 0; j < 4; j++) {
                if (MODE == 0) {
                    g1 = fmaf(dsr, g1, u[j]);
                    g2 = fmaf(dsr, g2, g1);
                    o[j] = psc * (g2 - g1);
                } else {
                    float v = u[j] + r - 10.0f;
                    float s = (v >= 0.f) ? 1.f : 0.f;
                    r = dref * (r - 20.f * s);
                    g1 = fmaf(dsr, g1, s);
                    g2 = fmaf(dsr, g2, g1);
                    o[j] = psc * (g2 - g1);
                }
            }
            *(float4*)(ob + c * CH + f * 4) = make_float4(o[0], o[1], o[2], o[3]);
        }
    };

    load(A, 0);
    for (int c = 0; c < NC; c += 2) {
        load(B, c + 1);
        compute(A, c);
        if (c + 2 < NC) load(A, c + 2);
        compute(B, c + 1);
    }
}

// ---------------------------------------------------------------------------
// Fused conv + spike/psp epilogue over ZERO-PADDED input, with an explicitly
// SOFTWARE-PIPELINED ic loop: two named column buffers (vA/vB), advance by 2,
// so every iteration's LDG.128s are in flight one full FFMA2 burst before
// their consumers. #pragma unroll 1 bounds code size for large IC.
// Block = 64 threads (TW=4 t each), PX=2 x-adjacent pixels, OCG channels.
// EPI = 1: spike + psp.  EPI = 4: spike only (final layer).
// ---------------------------------------------------------------------------
template<int IC, int KS, int OCG, int EPI, int H, int W, int OC>
__global__ __launch_bounds__(64)
void conv_kernel(const float* __restrict__ in, const float* __restrict__ wgt,
                 float* __restrict__ out)
{
    constexpr int PAD  = KS / 2;
    constexpr int Hp   = H + 2 * PAD;
    constexpr int Wp   = W + 2 * PAD;
    constexpr int PX   = 2;
    constexpr int NCOL = KS + PX - 1;
    constexpr int W2   = W / 2;
    constexpr int SW_BYTES = IC * KS * KS * OCG * 8;
    constexpr int SA_BYTES = PX * OCG * 260 * 4;
    constexpr int SM_BYTES = SW_BYTES > SA_BYTES ? SW_BYTES : SA_BYTES;
    __shared__ __align__(16) unsigned char smem_raw[SM_BYTES];
    unsigned long long* sw = (unsigned long long*)smem_raw;
    float* sa = (float*)smem_raw;           // rows: [PX*OCG][260]

    int tid = threadIdx.x;
    int t   = tid * 4;

    int pp = blockIdx.x;
    int x0 = (pp % W2) * 2;
    int y  = (pp / W2) % H;
    int b  = pp / (W2 * H);
    int oc0 = blockIdx.y * OCG;

    for (int i = tid; i < IC * KS * KS * OCG; i += 64) {
        int k = i / OCG, o = i % OCG;
        unsigned u = __float_as_uint(wgt[(long)(oc0 + o) * IC * KS * KS + k]);
        sw[i] = ((unsigned long long)u << 32) | u;
    }
    __syncthreads();

    unsigned long long acc[PX][OCG][2];
    #pragma unroll
    for (int p = 0; p < PX; p++)
        #pragma unroll
        for (int o = 0; o < OCG; o++) { acc[p][o][0] = 0ull; acc[p][o][1] = 0ull; }

    constexpr long planeTp = (long)Hp * Wp * TT;
    const float* inb = in + ((long)b * IC * Hp + y) * (long)Wp * TT + (long)x0 * TT + t;

    // MAC burst for one (kh, ic) using a preloaded column buffer.
    auto mac = [&](const ulonglong2 (&v)[NCOL], int kh, int ic) {
        #pragma unroll
        for (int dx = 0; dx < KS; dx++) {
            const unsigned long long* swp = &sw[(ic * KS * KS + kh * KS + dx) * OCG];
            if constexpr (OCG % 2 == 0) {
                #pragma unroll
                for (int o = 0; o < OCG; o += 2) {
                    ulonglong2 wv = *(const ulonglong2*)(swp + o);
                    #pragma unroll
                    for (int p = 0; p < PX; p++) {
                        ffma2(acc[p][o    ][0], wv.x, v[dx + p].x);
                        ffma2(acc[p][o    ][1], wv.x, v[dx + p].y);
                        ffma2(acc[p][o + 1][0], wv.y, v[dx + p].x);
                        ffma2(acc[p][o + 1][1], wv.y, v[dx + p].y);
                    }
                }
            } else {
                #pragma unroll
                for (int o = 0; o < OCG; o++) {
                    unsigned long long wv = swp[o];
                    #pragma unroll
                    for (int p = 0; p < PX; p++) {
                        ffma2(acc[p][o][0], wv, v[dx + p].x);
                        ffma2(acc[p][o][1], wv, v[dx + p].y);
                    }
                }
            }
        }
    };

    auto loadcols = [&](ulonglong2 (&v)[NCOL], const float* base) {
        #pragma unroll
        for (int j = 0; j < NCOL; j++)
            v[j] = *(const ulonglong2*)(base + j * TT);
    };

    #pragma unroll
    for (int kh = 0; kh < KS; kh++) {
        const float* rp = inb + (long)kh * Wp * TT;
        if constexpr (IC == 1) {
            ulonglong2 v[NCOL];
            loadcols(v, rp);
            mac(v, kh, 0);
        } else {
            ulonglong2 vA[NCOL], vB[NCOL];
            loadcols(vA, rp);                       // ic = 0
            #pragma unroll 1
            for (int ic = 0; ic < IC; ic += 2) {
                loadcols(vB, rp + (long)(ic + 1) * planeTp);   // prefetch ic+1
                mac(vA, kh, ic);
                int icn = (ic + 2 < IC) ? (ic + 2) : ic;       // clamped (junk ok)
                loadcols(vA, rp + (long)icn * planeTp);        // prefetch ic+2
                mac(vB, kh, ic + 1);
            }
        }
    }

    // All threads done reading sw -> safe to overwrite with sa.
    __syncthreads();

    #pragma unroll
    for (int p = 0; p < PX; p++)
        #pragma unroll
        for (int o = 0; o < OCG; o++) {
            float* sap = sa + (p * OCG + o) * 260 + t;
            *(float2*)(sap    ) = *(float2*)&acc[p][o][0];
            *(float2*)(sap + 2) = *(float2*)&acc[p][o][1];
        }
    __syncthreads();

    // Per-(pixel,channel) serial recurrence over T (PX*OCG threads).
    if (tid < PX * OCG) {
        const float dsr  = 0.9048374180359595f;
        const float psc  = 0.27182818284590452f;
        const float dref = 0.36787944117144233f;
        float* row = sa + tid * 260;
        float g1 = 0.f, g2 = 0.f, r = 0.f;
        float4 nxt = *(float4*)row;
        for (int tt = 0; tt < TT; tt += 4) {
            float4 a = nxt;
            if (tt + 4 < TT) nxt = *(float4*)(row + tt + 4);
            float u[4] = {a.x, a.y, a.z, a.w};
            float o4[4];
            #pragma unroll
            for (int j = 0; j < 4; j++) {
                float v = u[j] + r - 10.0f;
                float s = (v >= 0.f) ? 1.f : 0.f;
                r = dref * (r - 20.f * s);
                if (EPI == 4) {
                    o4[j] = s;
                } else {
                    g1 = fmaf(dsr, g1, s);
                    g2 = fmaf(dsr, g2, g1);
                    o4[j] = psc * (g2 - g1);
                }
            }
            *(float4*)(row + tt) = make_float4(o4[0], o4[1], o4[2], o4[3]);
        }
    }
    __syncthreads();

    // Coalesced float4 stores to the UNPADDED output layout.
    constexpr long planeT = (long)H * W * TT;
    #pragma unroll
    for (int p = 0; p < PX; p++) {
        float* ob = out + ((long)b * OC + oc0) * planeT + ((long)y * W + x0 + p) * TT + t;
        #pragma unroll
        for (int o = 0; o < OCG; o++)
            *(float4*)(ob + o * planeT) = *(const float4*)(sa + (p * OCG + o) * 260 + t);
    }
}

// ---------------------------------------------------------------------------
// 10 launches; every tensor has a dedicated workspace region (halos stay 0).
// ---------------------------------------------------------------------------
extern "C" void kernel_launch(void* const* d_in, const int* in_sizes, int n_in,
                              void* d_out, int out_size)
{
    const float* inp = (const float*)d_in[0];  // [4,1,32,32,256]
    const float* w1  = (const float*)d_in[1];  // [16,1,5,5,1]
    const float* w2  = (const float*)d_in[2];  // [32,16,3,3,1]
    const float* w3  = (const float*)d_in[3];  // [64,32,3,3,1]
    const float* w4  = (const float*)d_in[4];  // [32,64,3,3,1]
    const float* wo  = (const float*)d_in[5];  // [1,32,1,1,1]
    float* out = (float*)d_out;

    float* WS;
    cudaGetSymbolAddress((void**)&WS, g_ws);
    float* P0 = WS + O_P0;  float* P1 = WS + O_P1;
    float* P2 = WS + O_P2;  float* P3 = WS + O_P3;
    float* P4 = WS + O_P4;  float* P5 = WS + O_P5;
    float* P6 = WS + O_P6;  float* P7 = WS + O_P7;
    float* P8 = WS + O_P8;

    // P0 = psp(input), padded 2 for conv1
    dyn_kernel<0, 32, 32, 2><<<128, 32>>>(inp, P0, 4096);

    // P1 = spike/psp(conv1(P0))
    conv_kernel<1, 5, 8, 1, 32, 32, 16><<<dim3(2048, 2), 64>>>(P0, w1, P1);

    // P2 = pool+spike+psp(P1), padded 1 for conv2   [4,16,16,16]
    dyn_kernel<2, 16, 16, 1><<<256, 64>>>(P1, P2, 16384);

    // P3 = spike/psp(conv2(P2))
    conv_kernel<16, 3, 4, 1, 16, 16, 32><<<dim3(512, 8), 64>>>(P2, w2, P3);

    // P4 = pool+spike+psp(P3), padded 1 for conv3   [4,32,8,8]
    dyn_kernel<2, 8, 8, 1><<<256, 32>>>(P3, P4, 8192);

    // P5 = spike/psp(conv3(P4))
    conv_kernel<32, 3, 4, 1, 8, 8, 64><<<dim3(128, 16), 64>>>(P4, w3, P5);

    // P6 = up+spike+psp(P5), padded 1 for conv4   [4,64,16,16]
    dyn_kernel<3, 16, 16, 1><<<512, 128>>>(P5, P6, 65536);

    // P7 = spike/psp(conv4(P6))
    conv_kernel<64, 3, 4, 1, 16, 16, 32><<<dim3(512, 8), 64>>>(P6, w4, P7);

    // P8 = up+spike+psp(P7), unpadded (conv_out is 1x1)   [4,32,32,32]
    dyn_kernel<3, 32, 32, 0><<<1024, 128>>>(P7, P8, 131072);

    // out = spike(conv_out(P8))
    conv_kernel<32, 1, 1, 4, 32, 32, 1><<<dim3(2048, 1), 64>>>(P8, wo, out);
}